// round 2
// baseline (speedup 1.0000x reference)
#include <cuda_runtime.h>
#include <cstdint>

// Problem constants
#define B_TOT   4096
#define K_STEPS 512
#define U_DIM   3
#define P_DIM   5
#define H_DIM   128
#define L_DIM   32
#define M_ROWS  32      // batch rows per CTA
#define THREADS 256

// Transposed-weight scratch (filled by prep kernel each launch; deterministic)
__device__ __align__(16) float g_whh_t[128 * 384];  // [kk][o]
__device__ __align__(16) float g_wih_t[32 * 384];   // [l][o]

__global__ void prep_kernel(const float* __restrict__ W_ih,
                            const float* __restrict__ W_hh) {
    int i = blockIdx.x * blockDim.x + threadIdx.x;
    if (i < 384 * 128) {
        int o = i / 128, kk = i % 128;
        g_whh_t[kk * 384 + o] = W_hh[i];
    }
    if (i < 384 * 32) {
        int o = i / 32, l = i % 32;
        g_wih_t[l * 384 + o] = W_ih[i];
    }
}

__device__ __forceinline__ float sigmoidf_(float x) {
    x = fminf(fmaxf(x, -30.f), 30.f);
    return __fdividef(1.f, 1.f + __expf(-x));
}
__device__ __forceinline__ float tanhf_(float x) {
    x = fminf(fmaxf(x, -15.f), 15.f);
    float e = __expf(2.f * x);
    return __fdividef(e - 1.f, e + 1.f);
}

__device__ __forceinline__ void rhs5(const float* __restrict__ y,
                                     const float* __restrict__ th,
                                     float* __restrict__ d) {
    float A = y[0], D = y[1], G = y[2], J = y[3], M = y[4];
    float f1 = th[0] * A - th[4] * D;
    float f2 = th[1] * D - th[5] * G;
    float f3 = th[2] * G - th[6] * J;
    float f4 = th[3] * J - th[7] * M;
    d[0] = -f1;
    d[1] = f1 - f2;
    d[2] = f2 - f3;
    d[3] = f3 - f4;
    d[4] = f4;
}

// smem layout (floats):
//   whh   : 128*384 = 49152
//   h_t   : 128*36  = 4608   (h transposed: h_t[kk][r], pitch 36)
//   x_t   : 32*36   = 1152   (x transposed: x_t[l][r],  pitch 36)
//   y_s   : 32*8    = 256
//   th_s  : 32*8    = 256
//   u_s   : 32*4    = 128
//   dt_s  : 32
// total = 55584 floats = 222336 bytes
#define SM_TOTAL_FLOATS 55584

__global__ void __launch_bounds__(THREADS, 1)
rnn_main(const float* __restrict__ y0,
         const float* __restrict__ u_seq,
         const float* __restrict__ dt_seq,
         const float* __restrict__ lift_W,
         const float* __restrict__ lift_b,
         const float* __restrict__ b_ih,
         const float* __restrict__ b_hh,
         const float* __restrict__ head_W,
         const float* __restrict__ head_b,
         const float* __restrict__ ujump,
         float* __restrict__ y_out,
         float* __restrict__ theta_out) {
    extern __shared__ float sm[];
    float* whh  = sm;                 // 49152
    float* h_t  = whh + 49152;        // 4608
    float* x_t  = h_t + 4608;         // 1152
    float* y_s  = x_t + 1152;         // 256
    float* th_s = y_s + 256;          // 256
    float* u_s  = th_s + 256;         // 128
    float* dt_s = u_s + 128;          // 32

    const int t  = threadIdx.x;
    const int jg = t & 31;            // j-group: j = 4*jg + c
    const int rg = t >> 5;            // row-group: r = 4*rg + rr (== warp id)
    const int R0 = blockIdx.x * M_ROWS;

    // Stage weights into smem (coalesced float4)
    {
        const float4* src = (const float4*)g_whh_t;
        float4* dst = (float4*)whh;
        #pragma unroll 4
        for (int i = t; i < 49152 / 4; i += THREADS) dst[i] = src[i];
    }
    for (int i = t; i < 4608; i += THREADS) h_t[i] = 0.f;
    if (t < M_ROWS) {
        #pragma unroll
        for (int i = 0; i < 5; ++i)
            y_s[t * 8 + i] = y0[(R0 + t) * 5 + i] + 0.01f;
    }

    // Per-thread gate biases (fixed j's for the whole sequence)
    float bR[4], bZ[4], bNI[4], bNH[4];
    #pragma unroll
    for (int c = 0; c < 4; ++c) {
        int j = 4 * jg + c;
        bR[c]  = b_ih[j] + b_hh[j];
        bZ[c]  = b_ih[128 + j] + b_hh[128 + j];
        bNI[c] = b_ih[256 + j];
        bNH[c] = b_hh[256 + j];
    }
    __syncthreads();

    for (int k = 0; k < K_STEPS; ++k) {
        // ---------- stage 1: lift + silu -> x_t[l][r] ----------
        {
            int r  = t & 31;
            int lg = t >> 5;
            float f[8];
            const float* up = u_seq + ((size_t)(R0 + r) * K_STEPS + k) * U_DIM;
            f[0] = up[0]; f[1] = up[1]; f[2] = up[2];
            #pragma unroll
            for (int i = 0; i < 5; ++i) f[3 + i] = y_s[r * 8 + i];
            if (lg == 0) {
                u_s[r * 4 + 0] = f[0];
                u_s[r * 4 + 1] = f[1];
                u_s[r * 4 + 2] = f[2];
                dt_s[r] = dt_seq[(size_t)(R0 + r) * K_STEPS + k];
            }
            #pragma unroll
            for (int c = 0; c < 4; ++c) {
                int l = lg * 4 + c;
                float acc = lift_b[l];
                #pragma unroll
                for (int q = 0; q < 8; ++q)
                    acc = fmaf(lift_W[l * 8 + q], f[q], acc);
                x_t[l * 36 + r] = acc * sigmoidf_(acc);
            }
        }
        __syncthreads();

        // ---------- stage 2: gi + gh GEMMs, gates, h update ----------
        float aR[4][4], aZ[4][4], aNI[4][4], aNH[4][4];
        #pragma unroll
        for (int rr = 0; rr < 4; ++rr)
            #pragma unroll
            for (int c = 0; c < 4; ++c) {
                aR[rr][c]  = bR[c];
                aZ[rr][c]  = bZ[c];
                aNI[rr][c] = bNI[c];
                aNH[rr][c] = bNH[c];
            }

        // gi: x (32-long K), weights from L2-resident transposed table
        #pragma unroll 4
        for (int l = 0; l < 32; ++l) {
            const float4 wr = __ldg((const float4*)(g_wih_t + l * 384 + 4 * jg));
            const float4 wz = __ldg((const float4*)(g_wih_t + l * 384 + 128 + 4 * jg));
            const float4 wn = __ldg((const float4*)(g_wih_t + l * 384 + 256 + 4 * jg));
            const float4 xb = *(const float4*)(x_t + l * 36 + 4 * rg);
            const float xv[4] = {xb.x, xb.y, xb.z, xb.w};
            const float wrv[4] = {wr.x, wr.y, wr.z, wr.w};
            const float wzv[4] = {wz.x, wz.y, wz.z, wz.w};
            const float wnv[4] = {wn.x, wn.y, wn.z, wn.w};
            #pragma unroll
            for (int rr = 0; rr < 4; ++rr)
                #pragma unroll
                for (int c = 0; c < 4; ++c) {
                    aR[rr][c]  = fmaf(xv[rr], wrv[c], aR[rr][c]);
                    aZ[rr][c]  = fmaf(xv[rr], wzv[c], aZ[rr][c]);
                    aNI[rr][c] = fmaf(xv[rr], wnv[c], aNI[rr][c]);
                }
        }

        // gh: h (128-long K), weights from smem
        #pragma unroll 2
        for (int kk = 0; kk < 128; ++kk) {
            const float4 wr = *(const float4*)(whh + kk * 384 + 4 * jg);
            const float4 wz = *(const float4*)(whh + kk * 384 + 128 + 4 * jg);
            const float4 wn = *(const float4*)(whh + kk * 384 + 256 + 4 * jg);
            const float4 hb = *(const float4*)(h_t + kk * 36 + 4 * rg);
            const float hv[4] = {hb.x, hb.y, hb.z, hb.w};
            const float wrv[4] = {wr.x, wr.y, wr.z, wr.w};
            const float wzv[4] = {wz.x, wz.y, wz.z, wz.w};
            const float wnv[4] = {wn.x, wn.y, wn.z, wn.w};
            #pragma unroll
            for (int rr = 0; rr < 4; ++rr)
                #pragma unroll
                for (int c = 0; c < 4; ++c) {
                    aR[rr][c]  = fmaf(hv[rr], wrv[c], aR[rr][c]);
                    aZ[rr][c]  = fmaf(hv[rr], wzv[c], aZ[rr][c]);
                    aNH[rr][c] = fmaf(hv[rr], wnv[c], aNH[rr][c]);
                }
        }

        // h values this thread owns (for z*h term)
        float hown[4][4];
        #pragma unroll
        for (int c = 0; c < 4; ++c)
            #pragma unroll
            for (int rr = 0; rr < 4; ++rr)
                hown[rr][c] = h_t[(4 * jg + c) * 36 + 4 * rg + rr];

        float hnew[4][4];
        #pragma unroll
        for (int rr = 0; rr < 4; ++rr)
            #pragma unroll
            for (int c = 0; c < 4; ++c) {
                float gr = sigmoidf_(aR[rr][c]);
                float gz = sigmoidf_(aZ[rr][c]);
                float gn = tanhf_(fmaf(gr, aNH[rr][c], aNI[rr][c]));
                hnew[rr][c] = (1.f - gz) * gn + gz * hown[rr][c];
            }

        __syncthreads();  // all reads of h_t complete
        #pragma unroll
        for (int c = 0; c < 4; ++c)
            #pragma unroll
            for (int rr = 0; rr < 4; ++rr)
                h_t[(4 * jg + c) * 36 + 4 * rg + rr] = hnew[rr][c];
        __syncthreads();

        // ---------- stage 3: head -> theta ----------
        {
            int r = t >> 3, c8 = t & 7;
            float acc = head_b[c8];
            #pragma unroll 4
            for (int j = 0; j < 128; j += 4) {
                const float4 w = __ldg((const float4*)(head_W + c8 * 128 + j));
                acc = fmaf(w.x, h_t[(j + 0) * 36 + r], acc);
                acc = fmaf(w.y, h_t[(j + 1) * 36 + r], acc);
                acc = fmaf(w.z, h_t[(j + 2) * 36 + r], acc);
                acc = fmaf(w.w, h_t[(j + 3) * 36 + r], acc);
            }
            float th = 0.01f + 2.99f * sigmoidf_(acc);
            th_s[r * 8 + c8] = th;
            theta_out[(((size_t)(R0 + r)) * K_STEPS + k) * 8 + c8] = th;
        }
        __syncthreads();

        // ---------- stage 4: RK4 ODE (one lane per row) ----------
        if (t < 32) {
            int r = t;
            float y[5];
            #pragma unroll
            for (int i = 0; i < 5; ++i) y[i] = y_s[r * 8 + i];
            float u0 = u_s[r * 4 + 0], u1 = u_s[r * 4 + 1], u2 = u_s[r * 4 + 2];
            #pragma unroll
            for (int p = 0; p < 5; ++p)
                y[p] += u0 * ujump[p] + u1 * ujump[5 + p] + u2 * ujump[10 + p];
            float th[8];
            #pragma unroll
            for (int i = 0; i < 8; ++i) th[i] = th_s[r * 8 + i];
            float hs = dt_s[r] * 0.1f;
            float hh = 0.5f * hs;
            float h6 = hs * (1.f / 6.f);
            for (int s = 0; s < 10; ++s) {
                float k1[5], k2[5], k3[5], k4[5], yt[5];
                rhs5(y, th, k1);
                #pragma unroll
                for (int i = 0; i < 5; ++i) yt[i] = fmaf(hh, k1[i], y[i]);
                rhs5(yt, th, k2);
                #pragma unroll
                for (int i = 0; i < 5; ++i) yt[i] = fmaf(hh, k2[i], y[i]);
                rhs5(yt, th, k3);
                #pragma unroll
                for (int i = 0; i < 5; ++i) yt[i] = fmaf(hs, k3[i], y[i]);
                rhs5(yt, th, k4);
                #pragma unroll
                for (int i = 0; i < 5; ++i) {
                    float incr = k1[i] + 2.f * k2[i] + 2.f * k3[i] + k4[i];
                    y[i] = fmaxf(fmaf(h6, incr, y[i]), 0.f);
                }
            }
            #pragma unroll
            for (int i = 0; i < 5; ++i) {
                y_s[r * 8 + i] = y[i];
                y_out[(((size_t)(R0 + r)) * K_STEPS + k) * 5 + i] = y[i];
            }
        }
        __syncthreads();
    }
}

extern "C" void kernel_launch(void* const* d_in, const int* in_sizes, int n_in,
                              void* d_out, int out_size) {
    const float* y0     = (const float*)d_in[0];
    const float* u_seq  = (const float*)d_in[1];
    const float* dt_seq = (const float*)d_in[2];
    const float* lift_W = (const float*)d_in[3];
    const float* lift_b = (const float*)d_in[4];
    const float* W_ih   = (const float*)d_in[5];
    const float* W_hh   = (const float*)d_in[6];
    const float* b_ih   = (const float*)d_in[7];
    const float* b_hh   = (const float*)d_in[8];
    const float* head_W = (const float*)d_in[9];
    const float* head_b = (const float*)d_in[10];
    const float* ujump  = (const float*)d_in[11];

    float* y_out     = (float*)d_out;
    float* theta_out = y_out + (size_t)B_TOT * K_STEPS * 5;

    prep_kernel<<<(384 * 128 + 255) / 256, 256>>>(W_ih, W_hh);

    size_t smem_bytes = (size_t)SM_TOTAL_FLOATS * sizeof(float);  // 222336
    cudaFuncSetAttribute(rnn_main, cudaFuncAttributeMaxDynamicSharedMemorySize,
                         (int)smem_bytes);
    rnn_main<<<B_TOT / M_ROWS, THREADS, smem_bytes>>>(
        y0, u_seq, dt_seq, lift_W, lift_b, b_ih, b_hh, head_W, head_b, ujump,
        y_out, theta_out);
}

// round 3
// speedup vs baseline: 1.0945x; 1.0945x over previous
#include <cuda_runtime.h>
#include <cstdint>

#define B_TOT   4096
#define K_STEPS 512
#define U_DIM   3
#define P_DIM   5
#define H_DIM   128
#define L_DIM   32
#define M_ROWS  32
#define THREADS 256

typedef unsigned long long u64;

// Transposed-weight scratch (filled by prep kernel each launch; deterministic)
__device__ __align__(16) float g_whh_t[128 * 384];  // [kk][gate*128 + j]
__device__ __align__(16) float g_wih_j[128 * 96];   // [j][gate*32 + l]

__global__ void prep_kernel(const float* __restrict__ W_ih,
                            const float* __restrict__ W_hh) {
    int i = blockIdx.x * blockDim.x + threadIdx.x;
    if (i < 384 * 128) {
        int o = i / 128, kk = i % 128;
        g_whh_t[kk * 384 + o] = W_hh[o * 128 + kk];
    }
    if (i < 128 * 96) {
        int j = i / 96, rem = i % 96;
        int g = rem / 32, l = rem % 32;
        g_wih_j[i] = W_ih[(g * 128 + j) * 32 + l];
    }
}

__device__ __forceinline__ float sigmoidf_(float x) {
    x = fminf(fmaxf(x, -30.f), 30.f);
    return __fdividef(1.f, 1.f + __expf(-x));
}
__device__ __forceinline__ float tanhf_(float x) {
    x = fminf(fmaxf(x, -15.f), 15.f);
    float e = __expf(2.f * x);
    return __fdividef(e - 1.f, e + 1.f);
}

__device__ __forceinline__ u64 pack2(float a, float b) {
    u64 r; asm("mov.b64 %0,{%1,%2};" : "=l"(r) : "f"(a), "f"(b)); return r;
}
__device__ __forceinline__ u64 dup2(float a) { return pack2(a, a); }
__device__ __forceinline__ void unpack2(u64 v, float& a, float& b) {
    asm("mov.b64 {%0,%1},%2;" : "=f"(a), "=f"(b) : "l"(v));
}
__device__ __forceinline__ u64 fma2(u64 a, u64 b, u64 c) {
    u64 d; asm("fma.rn.f32x2 %0,%1,%2,%3;" : "=l"(d) : "l"(a), "l"(b), "l"(c));
    return d;
}

__device__ __forceinline__ void rhs5(const float* __restrict__ y,
                                     const float* __restrict__ th,
                                     float* __restrict__ d) {
    float A = y[0], D = y[1], G = y[2], J = y[3], M = y[4];
    float f1 = th[0] * A - th[4] * D;
    float f2 = th[1] * D - th[5] * G;
    float f3 = th[2] * G - th[6] * J;
    float f4 = th[3] * J - th[7] * M;
    d[0] = -f1; d[1] = f1 - f2; d[2] = f2 - f3; d[3] = f3 - f4; d[4] = f4;
}

// smem (floats): whh 49152 | h_t 128*36 | x_t 32*36 | y_s 256 | th_s 256 | u_s 128 | dt_s 32
#define SM_TOTAL_FLOATS 55584

__global__ void __launch_bounds__(THREADS, 1)
rnn_main(const float* __restrict__ y0,
         const float* __restrict__ u_seq,
         const float* __restrict__ dt_seq,
         const float* __restrict__ lift_W,
         const float* __restrict__ lift_b,
         const float* __restrict__ b_ih,
         const float* __restrict__ b_hh,
         const float* __restrict__ head_W,
         const float* __restrict__ head_b,
         const float* __restrict__ ujump,
         float* __restrict__ y_out,
         float* __restrict__ theta_out) {
    extern __shared__ float sm[];
    float* whh  = sm;                 // 49152
    float* h_t  = whh + 49152;        // 4608 (pitch 36)
    float* x_t  = h_t + 4608;         // 1152 (pitch 36)
    float* y_s  = x_t + 1152;         // 256
    float* th_s = y_s + 256;          // 256
    float* u_s  = th_s + 256;         // 128
    float* dt_s = u_s + 128;          // 32

    const int t    = threadIdx.x;
    const int w    = t >> 5;
    const int lane = t & 31;
    const int jloc = lane >> 1;
    const int j    = w * 16 + jloc;       // this thread's hidden index
    const int rh   = (lane & 1) << 4;     // row half: 0 or 16
    const int R0   = blockIdx.x * M_ROWS;

    // Stage weights into smem
    {
        const float4* src = (const float4*)g_whh_t;
        float4* dst = (float4*)whh;
        #pragma unroll 4
        for (int i = t; i < 49152 / 4; i += THREADS) dst[i] = src[i];
    }
    for (int i = t; i < 4608; i += THREADS) h_t[i] = 0.f;
    if (t < M_ROWS) {
        #pragma unroll
        for (int i = 0; i < 5; ++i)
            y_s[t * 8 + i] = y0[(R0 + t) * 5 + i] + 0.01f;
    }

    // Per-thread biases (j fixed for whole sequence), pre-duplicated
    const u64 bR2  = dup2(b_ih[j] + b_hh[j]);
    const u64 bZ2  = dup2(b_ih[128 + j] + b_hh[128 + j]);
    const u64 bNI2 = dup2(b_ih[256 + j]);
    const u64 bNH2 = dup2(b_hh[256 + j]);
    const float* wj = g_wih_j + j * 96;
    __syncthreads();

    for (int k = 0; k < K_STEPS; ++k) {
        // ---------- stage 1: lift + silu -> x_t[l][r] ----------
        {
            int r  = t & 31;
            int lg = t >> 5;
            float f[8];
            const float* up = u_seq + ((size_t)(R0 + r) * K_STEPS + k) * U_DIM;
            f[0] = up[0]; f[1] = up[1]; f[2] = up[2];
            #pragma unroll
            for (int i = 0; i < 5; ++i) f[3 + i] = y_s[r * 8 + i];
            if (lg == 0) {
                u_s[r * 4 + 0] = f[0];
                u_s[r * 4 + 1] = f[1];
                u_s[r * 4 + 2] = f[2];
                dt_s[r] = dt_seq[(size_t)(R0 + r) * K_STEPS + k];
            }
            #pragma unroll
            for (int c = 0; c < 4; ++c) {
                int l = lg * 4 + c;
                float acc = lift_b[l];
                #pragma unroll
                for (int q = 0; q < 8; ++q)
                    acc = fmaf(lift_W[l * 8 + q], f[q], acc);
                x_t[l * 36 + r] = acc * sigmoidf_(acc);
            }
        }
        __syncthreads();

        // ---------- stage 2: GEMMs (f32x2, row pairs packed) ----------
        u64 aR[8], aZ[8], aNI[8], aNH[8];
        #pragma unroll
        for (int i = 0; i < 8; ++i) {
            aR[i] = bR2; aZ[i] = bZ2; aNI[i] = bNI2; aNH[i] = bNH2;
        }

        // gi: x in smem, W_ih[j] rows from L2 (prefetched by block)
        {
            float4 wR4 = __ldg((const float4*)(wj + 0));
            float4 wZ4 = __ldg((const float4*)(wj + 32));
            float4 wN4 = __ldg((const float4*)(wj + 64));
            #pragma unroll
            for (int l0 = 0; l0 < 32; l0 += 4) {
                float wRv[4], wZv[4], wNv[4];
                *(float4*)wRv = wR4; *(float4*)wZv = wZ4; *(float4*)wNv = wN4;
                if (l0 + 4 < 32) {
                    wR4 = __ldg((const float4*)(wj + l0 + 4));
                    wZ4 = __ldg((const float4*)(wj + 32 + l0 + 4));
                    wN4 = __ldg((const float4*)(wj + 64 + l0 + 4));
                }
                #pragma unroll
                for (int dl = 0; dl < 4; ++dl) {
                    const int l = l0 + dl;
                    const ulonglong2* xp = (const ulonglong2*)(x_t + l * 36 + rh);
                    ulonglong2 x01 = xp[0], x23 = xp[1], x45 = xp[2], x67 = xp[3];
                    u64 xv[8] = {x01.x, x01.y, x23.x, x23.y, x45.x, x45.y, x67.x, x67.y};
                    u64 wr2 = dup2(wRv[dl]), wz2 = dup2(wZv[dl]), wn2 = dup2(wNv[dl]);
                    #pragma unroll
                    for (int i = 0; i < 8; ++i) {
                        aR[i]  = fma2(xv[i], wr2, aR[i]);
                        aZ[i]  = fma2(xv[i], wz2, aZ[i]);
                        aNI[i] = fma2(xv[i], wn2, aNI[i]);
                    }
                }
            }
        }

        // gh: h + W_hh from smem. Warps own disjoint j-ranges -> no redundant
        // weight traffic; h loads are 2-group broadcasts.
        #pragma unroll 2
        for (int kk = 0; kk < 128; ++kk) {
            const float* wrow = whh + kk * 384 + j;
            u64 wr2 = dup2(wrow[0]);
            u64 wz2 = dup2(wrow[128]);
            u64 wn2 = dup2(wrow[256]);
            const ulonglong2* hp = (const ulonglong2*)(h_t + kk * 36 + rh);
            ulonglong2 h01 = hp[0], h23 = hp[1], h45 = hp[2], h67 = hp[3];
            u64 hv[8] = {h01.x, h01.y, h23.x, h23.y, h45.x, h45.y, h67.x, h67.y};
            #pragma unroll
            for (int i = 0; i < 8; ++i) {
                aR[i]  = fma2(hv[i], wr2, aR[i]);
                aZ[i]  = fma2(hv[i], wz2, aZ[i]);
                aNH[i] = fma2(hv[i], wn2, aNH[i]);
            }
        }

        // gates + h update (this thread owns h[j][rh..rh+15])
        float hn[16];
        {
            const ulonglong2* hop = (const ulonglong2*)(h_t + j * 36 + rh);
            ulonglong2 ho01 = hop[0], ho23 = hop[1], ho45 = hop[2], ho67 = hop[3];
            u64 hov[8] = {ho01.x, ho01.y, ho23.x, ho23.y, ho45.x, ho45.y, ho67.x, ho67.y};
            #pragma unroll
            for (int i = 0; i < 8; ++i) {
                float r0, r1, z0, z1, ni0, ni1, nh0, nh1, h0, h1;
                unpack2(aR[i], r0, r1);
                unpack2(aZ[i], z0, z1);
                unpack2(aNI[i], ni0, ni1);
                unpack2(aNH[i], nh0, nh1);
                unpack2(hov[i], h0, h1);
                float gr0 = sigmoidf_(r0), gr1 = sigmoidf_(r1);
                float gz0 = sigmoidf_(z0), gz1 = sigmoidf_(z1);
                float gn0 = tanhf_(fmaf(gr0, nh0, ni0));
                float gn1 = tanhf_(fmaf(gr1, nh1, ni1));
                hn[2 * i]     = (1.f - gz0) * gn0 + gz0 * h0;
                hn[2 * i + 1] = (1.f - gz1) * gn1 + gz1 * h1;
            }
        }

        __syncthreads();  // all reads of h_t complete
        {
            float4* hdst = (float4*)(h_t + j * 36 + rh);
            #pragma unroll
            for (int q = 0; q < 4; ++q)
                hdst[q] = make_float4(hn[4 * q], hn[4 * q + 1],
                                      hn[4 * q + 2], hn[4 * q + 3]);
        }
        __syncthreads();

        // ---------- stage 3: head -> theta ----------
        {
            int r = t >> 3, c8 = t & 7;
            float acc = head_b[c8];
            #pragma unroll 4
            for (int jj = 0; jj < 128; jj += 4) {
                const float4 wv = __ldg((const float4*)(head_W + c8 * 128 + jj));
                acc = fmaf(wv.x, h_t[(jj + 0) * 36 + r], acc);
                acc = fmaf(wv.y, h_t[(jj + 1) * 36 + r], acc);
                acc = fmaf(wv.z, h_t[(jj + 2) * 36 + r], acc);
                acc = fmaf(wv.w, h_t[(jj + 3) * 36 + r], acc);
            }
            float th = 0.01f + 2.99f * sigmoidf_(acc);
            th_s[r * 8 + c8] = th;
            theta_out[(((size_t)(R0 + r)) * K_STEPS + k) * 8 + c8] = th;
        }
        __syncthreads();

        // ---------- stage 4: RK4 ODE (one lane per row) ----------
        if (t < 32) {
            int r = t;
            float y[5];
            #pragma unroll
            for (int i = 0; i < 5; ++i) y[i] = y_s[r * 8 + i];
            float u0 = u_s[r * 4 + 0], u1 = u_s[r * 4 + 1], u2 = u_s[r * 4 + 2];
            #pragma unroll
            for (int p = 0; p < 5; ++p)
                y[p] += u0 * ujump[p] + u1 * ujump[5 + p] + u2 * ujump[10 + p];
            float th[8];
            #pragma unroll
            for (int i = 0; i < 8; ++i) th[i] = th_s[r * 8 + i];
            float hs = dt_s[r] * 0.1f;
            float hh = 0.5f * hs;
            float h6 = hs * (1.f / 6.f);
            for (int s = 0; s < 10; ++s) {
                float k1[5], k2[5], k3[5], k4[5], yt[5];
                rhs5(y, th, k1);
                #pragma unroll
                for (int i = 0; i < 5; ++i) yt[i] = fmaf(hh, k1[i], y[i]);
                rhs5(yt, th, k2);
                #pragma unroll
                for (int i = 0; i < 5; ++i) yt[i] = fmaf(hh, k2[i], y[i]);
                rhs5(yt, th, k3);
                #pragma unroll
                for (int i = 0; i < 5; ++i) yt[i] = fmaf(hs, k3[i], y[i]);
                rhs5(yt, th, k4);
                #pragma unroll
                for (int i = 0; i < 5; ++i) {
                    float incr = k1[i] + 2.f * k2[i] + 2.f * k3[i] + k4[i];
                    y[i] = fmaxf(fmaf(h6, incr, y[i]), 0.f);
                }
            }
            #pragma unroll
            for (int i = 0; i < 5; ++i) {
                y_s[r * 8 + i] = y[i];
                y_out[(((size_t)(R0 + r)) * K_STEPS + k) * 5 + i] = y[i];
            }
        }
        __syncthreads();
    }
}

extern "C" void kernel_launch(void* const* d_in, const int* in_sizes, int n_in,
                              void* d_out, int out_size) {
    const float* y0     = (const float*)d_in[0];
    const float* u_seq  = (const float*)d_in[1];
    const float* dt_seq = (const float*)d_in[2];
    const float* lift_W = (const float*)d_in[3];
    const float* lift_b = (const float*)d_in[4];
    const float* W_ih   = (const float*)d_in[5];
    const float* W_hh   = (const float*)d_in[6];
    const float* b_ih   = (const float*)d_in[7];
    const float* b_hh   = (const float*)d_in[8];
    const float* head_W = (const float*)d_in[9];
    const float* head_b = (const float*)d_in[10];
    const float* ujump  = (const float*)d_in[11];

    float* y_out     = (float*)d_out;
    float* theta_out = y_out + (size_t)B_TOT * K_STEPS * 5;

    prep_kernel<<<(384 * 128 + 255) / 256, 256>>>(W_ih, W_hh);

    size_t smem_bytes = (size_t)SM_TOTAL_FLOATS * sizeof(float);  // 222336
    cudaFuncSetAttribute(rnn_main, cudaFuncAttributeMaxDynamicSharedMemorySize,
                         (int)smem_bytes);
    rnn_main<<<B_TOT / M_ROWS, THREADS, smem_bytes>>>(
        y0, u_seq, dt_seq, lift_W, lift_b, b_ih, b_hh, head_W, head_b, ujump,
        y_out, theta_out);
}